// round 17
// baseline (speedup 1.0000x reference)
#include <cuda_runtime.h>
#include <cuda_fp16.h>
#include <math.h>
#include <cstdint>

// Problem constants
#define BATCH 8
#define SEQ   4096
#define CH    768
#define NH    12
#define HD    64
#define RM    128
#define BH    (BATCH*NH)
#define LAMBDA 0.3f
#define NSTEP 5
#define SPLITS 4
#define NCHUNK (SEQ/SPLITS)    // 1024

// ---------------- scratch ----------------------------------------------------
__device__ float g_PART[(size_t)SPLITS*BH*RM*(RM+HD)];
// fp16 split pairs / singles
__device__ __half g_XH1[(size_t)BATCH*SEQ*CH];       // x hi
__device__ __half g_XH2[(size_t)BATCH*SEQ*CH];       // x lo (q path only)
__device__ __half g_WQ1[(size_t)CH*CH];              // WqT single [n][k]
__device__ __half g_WV1[(size_t)CH*CH];              // WvT single
__device__ __half g_WP1[(size_t)CH*CH];              // WprojT single
__device__ __half g_QB1[(size_t)BH*SEQ*HD];          // qs pair [bh][n][d]
__device__ __half g_QB2[(size_t)BH*SEQ*HD];
__device__ __half g_RT1[(size_t)NH*RM*HD];           // R^T pair [h][m][d]
__device__ __half g_RT2[(size_t)NH*RM*HD];
__device__ __half g_RF1[(size_t)BH*SEQ*RM];          // rf pair [bh][n][m]
__device__ __half g_RF2[(size_t)BH*SEQ*RM];
__device__ __half g_VB1[(size_t)BH*SEQ*HD];          // v single [bh][n][d]
__device__ __half g_ST1[(size_t)BH*HD*RM];           // (d*s)^T single [bh][d][m]
__device__ __half g_OC1[(size_t)BATCH*SEQ*CH];       // out-head single

// ---------------- helpers ------------------------------------------------------
__device__ __forceinline__ uint32_t smem_u32(const void* p) {
    uint32_t a;
    asm("{ .reg .u64 t; cvta.to.shared.u64 t, %1; cvt.u32.u64 %0, t; }"
        : "=r"(a) : "l"(p));
    return a;
}
__device__ __forceinline__ void ldmx4(uint32_t& r0, uint32_t& r1,
                                      uint32_t& r2, uint32_t& r3, uint32_t addr)
{
    asm volatile("ldmatrix.sync.aligned.m8n8.x4.shared.b16 {%0,%1,%2,%3}, [%4];"
                 : "=r"(r0), "=r"(r1), "=r"(r2), "=r"(r3) : "r"(addr));
}
__device__ __forceinline__ void ldmx4t(uint32_t* r, uint32_t addr)
{
    asm volatile("ldmatrix.sync.aligned.m8n8.x4.trans.shared.b16 {%0,%1,%2,%3}, [%4];"
                 : "=r"(r[0]), "=r"(r[1]), "=r"(r[2]), "=r"(r[3]) : "r"(addr));
}
__device__ __forceinline__ void mma_f16(float* c, const uint32_t* a,
                                        const uint32_t* b)
{
    asm volatile(
        "mma.sync.aligned.m16n8k16.row.col.f32.f16.f16.f32 "
        "{%0,%1,%2,%3}, {%4,%5,%6,%7}, {%8,%9}, {%0,%1,%2,%3};"
        : "+f"(c[0]), "+f"(c[1]), "+f"(c[2]), "+f"(c[3])
        : "r"(a[0]), "r"(a[1]), "r"(a[2]), "r"(a[3]), "r"(b[0]), "r"(b[1]));
}
__device__ __forceinline__ void split2h(float v, __half& h, __half& l)
{
    h = __float2half(v);
    l = __float2half(v - __half2float(h));
}
__device__ __forceinline__ void cpa16(uint32_t saddr, const void* g)
{
    asm volatile("cp.async.cg.shared.global [%0], [%1], 16;"
                 :: "r"(saddr), "l"(g));
}
#define CP_COMMIT() asm volatile("cp.async.commit_group;")
#define CP_WAIT1()  asm volatile("cp.async.wait_group 1;")
#define CP_WAIT0()  asm volatile("cp.async.wait_group 0;")

#define PITCH 40
#define DG_TILE (128*PITCH)
#define DG_STAGE (3*DG_TILE)
#define DG_SMEM (2*DG_STAGE*2) // 61440 bytes

// ---------------- dense HMMA GEMM (fp16) -------------------------------------------
template<int EPI>
__global__ __launch_bounds__(256, 2)
void hmma_gemm(const float* __restrict__ bias, float* __restrict__ Cout, int Kdim)
{
    extern __shared__ uint16_t dsm[];

    const int tid  = threadIdx.x;
    const int wid  = tid >> 5;
    const int lane = tid & 31;
    const int wm   = wid & 1;
    const int wn   = wid >> 1;
    const int brow = blockIdx.y * 128;
    const int bcol = blockIdx.x * 128;

    const bool qmode = (EPI == 0) && (bcol < CH);
    const uint16_t* A1 = (EPI == 0) ? (const uint16_t*)g_XH1 : (const uint16_t*)g_OC1;
    const uint16_t* A2 = qmode ? (const uint16_t*)g_XH2 : nullptr;
    const uint16_t* B1;
    int bb0;
    if (EPI == 1)      { B1 = (const uint16_t*)g_WP1; bb0 = bcol; }
    else if (qmode)    { B1 = (const uint16_t*)g_WQ1; bb0 = bcol; }
    else               { B1 = (const uint16_t*)g_WV1; bb0 = bcol - CH; }
    const int NT = qmode ? 3 : 2;

    float acc[4][4][4];
#pragma unroll
    for (int i = 0; i < 4; i++)
#pragma unroll
        for (int j = 0; j < 4; j++)
#pragma unroll
            for (int q = 0; q < 4; q++) acc[i][j][q] = 0.f;

    const uint32_t smbase = smem_u32(dsm);
    const int arow = wm * 64 + (lane & 15);
    const int acolL = (lane >> 4) * 8;
    const int bn   = wn * 32 + (lane & 7) + ((lane >> 4) & 1) * 8;
    const int bkL  = ((lane >> 3) & 1) * 8;

    const int l_row0 = tid >> 2,        l_ch0 = (tid & 3) * 8;
    const int l_row1 = (tid + 256) >> 2, l_ch1 = ((tid + 256) & 3) * 8;

    auto load_stage = [&](int stage, int k0) {
        uint32_t sb = smbase + stage * DG_STAGE * 2;
        for (int t = 0; t < NT; t++) {
            const uint16_t* src;
            int rbase;
            if (qmode) {
                src = (t == 0) ? A1 : (t == 1) ? A2 : B1;
                rbase = (t < 2) ? brow : bb0;
            } else {
                src = (t == 0) ? A1 : B1;
                rbase = (t == 0) ? brow : bb0;
            }
            uint32_t tb = sb + t * DG_TILE * 2;
            cpa16(tb + (l_row0 * PITCH + l_ch0) * 2,
                  src + (size_t)(rbase + l_row0) * Kdim + k0 + l_ch0);
            cpa16(tb + (l_row1 * PITCH + l_ch1) * 2,
                  src + (size_t)(rbase + l_row1) * Kdim + k0 + l_ch1);
        }
    };

    const int nchunk = Kdim >> 5;
    load_stage(0, 0);
    CP_COMMIT();

    for (int kc = 0; kc < nchunk; kc++) {
        if (kc + 1 < nchunk) load_stage((kc + 1) & 1, (kc + 1) << 5);
        CP_COMMIT();
        CP_WAIT1();
        __syncthreads();

        const uint32_t sb = smbase + (kc & 1) * DG_STAGE * 2;
        const uint32_t as1 = sb;
        const uint32_t as2 = sb + DG_TILE * 2;
        const uint32_t bs1 = qmode ? sb + 2 * DG_TILE * 2 : sb + DG_TILE * 2;
#pragma unroll
        for (int ks = 0; ks < 2; ks++) {
            const int acol = ks * 16 + acolL;
            const int bk   = ks * 16 + bkL;
            uint32_t a1[4][4], a2[4][4], b1[4][2];
#pragma unroll
            for (int mt = 0; mt < 4; mt++) {
                uint32_t off = ((arow + mt * 16) * PITCH + acol) * 2;
                ldmx4(a1[mt][0], a1[mt][1], a1[mt][2], a1[mt][3], as1 + off);
                if (qmode)
                    ldmx4(a2[mt][0], a2[mt][1], a2[mt][2], a2[mt][3], as2 + off);
            }
#pragma unroll
            for (int nt2 = 0; nt2 < 2; nt2++) {
                uint32_t off = ((bn + nt2 * 16) * PITCH + bk) * 2;
                ldmx4(b1[nt2 * 2][0], b1[nt2 * 2][1],
                      b1[nt2 * 2 + 1][0], b1[nt2 * 2 + 1][1], bs1 + off);
            }
#pragma unroll
            for (int mt = 0; mt < 4; mt++)
#pragma unroll
                for (int nt = 0; nt < 4; nt++) {
                    mma_f16(acc[mt][nt], a1[mt], b1[nt]);
                    if (qmode)
                        mma_f16(acc[mt][nt], a2[mt], b1[nt]);
                }
        }
        __syncthreads();
    }

    const int g  = lane >> 2;
    const int tg = lane & 3;
#pragma unroll
    for (int mt = 0; mt < 4; mt++)
#pragma unroll
        for (int nt = 0; nt < 4; nt++) {
#pragma unroll
            for (int half = 0; half < 2; half++) {
                int grow = brow + wm * 64 + mt * 16 + g + half * 8;
                int col  = bcol + wn * 32 + nt * 8 + tg * 2;
                float2 v = make_float2(acc[mt][nt][half * 2],
                                       acc[mt][nt][half * 2 + 1]);
                if (EPI == 0) {
                    int bb = grow >> 12, nn = grow & 4095;
                    if (col < CH) {
                        const float s = 0.35355339059327373f;  // hd^(-1/4)
                        v.x *= s; v.y *= s;
                        int h = col >> 6, dd = col & 63;
                        size_t adr = (((size_t)(bb * NH + h)) * SEQ + nn) * HD + dd;
                        __half h0, l0, h1, l1;
                        split2h(v.x, h0, l0); split2h(v.y, h1, l1);
                        *(__half2*)&g_QB1[adr] = __halves2half2(h0, h1);
                        *(__half2*)&g_QB2[adr] = __halves2half2(l0, l1);
                    } else {
                        int c2 = col - CH;
                        int h = c2 >> 6, dd = c2 & 63;
                        size_t adr = (((size_t)(bb * NH + h)) * SEQ + nn) * HD + dd;
                        *(__half2*)&g_VB1[adr] =
                            __halves2half2(__float2half(v.x), __float2half(v.y));
                    }
                } else {
                    v.x += bias[col];
                    v.y += bias[col + 1];
                    *(float2*)&Cout[(size_t)grow * CH + col] = v;
                }
            }
        }
}

// ---------------- conversion kernels -----------------------------------------
__global__ __launch_bounds__(256)
void conv_x_kernel(const float* __restrict__ x)
{
    size_t i = ((size_t)blockIdx.x * 256 + threadIdx.x) * 4;
    float4 v = *(const float4*)&x[i];
    __half h0, l0, h1, l1, h2, l2, h3, l3;
    split2h(v.x, h0, l0); split2h(v.y, h1, l1);
    split2h(v.z, h2, l2); split2h(v.w, h3, l3);
    *(__half2*)&g_XH1[i]     = __halves2half2(h0, h1);
    *(__half2*)&g_XH1[i + 2] = __halves2half2(h2, h3);
    *(__half2*)&g_XH2[i]     = __halves2half2(l0, l1);
    *(__half2*)&g_XH2[i + 2] = __halves2half2(l2, l3);
}

__global__ __launch_bounds__(256)
void conv_small(const float* __restrict__ wqkv, const float* __restrict__ wproj,
                const float* __restrict__ randm)
{
    int idx = blockIdx.x * 256 + threadIdx.x;
    if (idx < 2 * CH * CH) {
        int n = idx / CH, k = idx - n * CH;
        float v = wqkv[(size_t)k * (2 * CH) + n];
        if (n < CH) g_WQ1[(size_t)n * CH + k] = __float2half(v);
        else        g_WV1[(size_t)(n - CH) * CH + k] = __float2half(v);
    } else if (idx < 3 * CH * CH) {
        int i2 = idx - 2 * CH * CH;
        int n = i2 / CH, k = i2 - n * CH;
        g_WP1[i2] = __float2half(wproj[(size_t)k * CH + n]);
    } else {
        int i2 = idx - 3 * CH * CH;
        int h = i2 / (RM * HD);
        int r = i2 - h * (RM * HD);
        int m = r / HD, d = r - m * HD;
        float v = randm[((size_t)h * HD + d) * RM + m];
        __half hi, lo;
        split2h(v, hi, lo);
        g_RT1[i2] = hi;
        g_RT2[i2] = lo;
    }
}

// ---------------- rf via HMMA (fp16 3-term), staged coalesced stores -------------
#define RF_PITCH 72
#define RF_TILE (128*RF_PITCH)
#define RF_SMEM (4*RF_TILE*2)
#define RF_SPITCH 136

__global__ __launch_bounds__(256, 2)
void rf_hmma()
{
    extern __shared__ __half rsm[];
    __shared__ float rowq2[128];
    const int tid = threadIdx.x, wid = tid >> 5, lane = tid & 31;
    const int wm = wid & 1, wn = wid >> 1;
    const int bh = blockIdx.y, h = bh % NH;
    const int brow = blockIdx.x * 128;

    const __half* A1 = g_QB1 + ((size_t)bh * SEQ + brow) * HD;
    const __half* A2 = g_QB2 + ((size_t)bh * SEQ + brow) * HD;
    const __half* B1 = g_RT1 + (size_t)h * RM * HD;
    const __half* B2 = g_RT2 + (size_t)h * RM * HD;

    const uint32_t smbase = smem_u32(rsm);
#pragma unroll
    for (int t = 0; t < 4; t++) {
        const __half* src = (t == 0) ? A1 : (t == 1) ? A2 : (t == 2) ? B1 : B2;
        uint32_t dst = smbase + t * RF_TILE * 2;
#pragma unroll
        for (int u = 0; u < 4; u++) {
            int f = u * 256 + tid;
            int r = f >> 3, c = (f & 7) * 8;
            cpa16(dst + (r * RF_PITCH + c) * 2, src + (size_t)r * HD + c);
        }
    }
    CP_COMMIT();
    CP_WAIT0();
    __syncthreads();

    {
        int r = tid >> 1;
        int k0 = (tid & 1) * 32;
        const __half* q1 = rsm + r * RF_PITCH + k0;
        const __half* q2 = rsm + RF_TILE + r * RF_PITCH + k0;
        float s = 0.f;
#pragma unroll
        for (int k = 0; k < 32; k++) {
            float v = __half2float(q1[k]) + __half2float(q2[k]);
            s += v * v;
        }
        s += __shfl_xor_sync(0xffffffffu, s, 1);
        if (!(tid & 1)) rowq2[r] = s;
    }

    float acc[4][4][4];
#pragma unroll
    for (int i = 0; i < 4; i++)
#pragma unroll
        for (int j = 0; j < 4; j++)
#pragma unroll
            for (int q = 0; q < 4; q++) acc[i][j][q] = 0.f;

    const uint32_t as1 = smbase, as2 = smbase + RF_TILE * 2;
    const uint32_t bs1 = smbase + 2 * RF_TILE * 2, bs2 = smbase + 3 * RF_TILE * 2;
    const int arow = wm * 64 + (lane & 15);
    const int acolL = (lane >> 4) * 8;
    const int bn   = wn * 32 + (lane & 7) + ((lane >> 4) & 1) * 8;
    const int bkL  = ((lane >> 3) & 1) * 8;

#pragma unroll
    for (int ks = 0; ks < 4; ks++) {
        const int acol = ks * 16 + acolL;
        const int bk   = ks * 16 + bkL;
        uint32_t a1[4][4], a2[4][4], b1[4][2], b2[4][2];
#pragma unroll
        for (int mt = 0; mt < 4; mt++) {
            uint32_t off = ((arow + mt * 16) * RF_PITCH + acol) * 2;
            ldmx4(a1[mt][0], a1[mt][1], a1[mt][2], a1[mt][3], as1 + off);
            ldmx4(a2[mt][0], a2[mt][1], a2[mt][2], a2[mt][3], as2 + off);
        }
#pragma unroll
        for (int nt2 = 0; nt2 < 2; nt2++) {
            uint32_t off = ((bn + nt2 * 16) * RF_PITCH + bk) * 2;
            ldmx4(b1[nt2 * 2][0], b1[nt2 * 2][1],
                  b1[nt2 * 2 + 1][0], b1[nt2 * 2 + 1][1], bs1 + off);
            ldmx4(b2[nt2 * 2][0], b2[nt2 * 2][1],
                  b2[nt2 * 2 + 1][0], b2[nt2 * 2 + 1][1], bs2 + off);
        }
#pragma unroll
        for (int mt = 0; mt < 4; mt++)
#pragma unroll
            for (int nt = 0; nt < 4; nt++) {
                mma_f16(acc[mt][nt], a1[mt], b1[nt]);
                mma_f16(acc[mt][nt], a1[mt], b2[nt]);
                mma_f16(acc[mt][nt], a2[mt], b1[nt]);
            }
    }
    __syncthreads();

    __half* st1 = rsm;
    __half* st2 = rsm + 128 * RF_SPITCH;
    const int g  = lane >> 2;
    const int tg = lane & 3;
    const float sc = 0.08838834764831845f;  // 1/sqrt(128)
#pragma unroll
    for (int mt = 0; mt < 4; mt++)
#pragma unroll
        for (int nt = 0; nt < 4; nt++)
#pragma unroll
            for (int half = 0; half < 2; half++) {
                int row  = wm * 64 + mt * 16 + g + half * 8;
                int mcol = wn * 32 + nt * 8 + tg * 2;
                float base = -0.5f * rowq2[row];
                float v0 = __expf(acc[mt][nt][half * 2]     + base) * sc;
                float v1 = __expf(acc[mt][nt][half * 2 + 1] + base) * sc;
                __half h0, l0, h1, l1;
                split2h(v0, h0, l0); split2h(v1, h1, l1);
                *(__half2*)&st1[row * RF_SPITCH + mcol] = __halves2half2(h0, h1);
                *(__half2*)&st2[row * RF_SPITCH + mcol] = __halves2half2(l0, l1);
            }
    __syncthreads();

    size_t gbase = ((size_t)bh * SEQ + brow) * RM;
#pragma unroll
    for (int l = 0; l < 8; l++) {
        int f = tid + l * 256;
        int r = f >> 4, c = (f & 15) * 8;
        *(uint4*)(g_RF1 + gbase + (size_t)r * RM + c) =
            *(const uint4*)(st1 + r * RF_SPITCH + c);
        *(uint4*)(g_RF2 + gbase + (size_t)r * RM + c) =
            *(const uint4*)(st2 + r * RF_SPITCH + c);
    }
}

// ---------------- kk via fp16 2-term HMMA: full 128-j slab, B from A1 tile -------
#define KK_ROWS 64
#define KKK_A_TILE (KK_ROWS*136)
#define KKK_STAGE (2*KKK_A_TILE)
#define KKK_SMEM (2*KKK_STAGE*2)   // 69632 bytes

__global__ __launch_bounds__(256, 2)
void kk_hmma()
{
    extern __shared__ __half ksm[];
    const int tid = threadIdx.x, wid = tid >> 5, lane = tid & 31;
    const int bh = blockIdx.x, split = blockIdx.y;
    const int wm = wid >> 1, wn = wid & 1;

    size_t abase = ((size_t)bh * SEQ + (size_t)split * NCHUNK) * RM;
    const __half *a1 = g_RF1 + abase, *a2 = g_RF2 + abase;

    float acc[2][8][4];
#pragma unroll
    for (int i = 0; i < 2; i++)
#pragma unroll
        for (int j = 0; j < 8; j++)
#pragma unroll
            for (int q = 0; q < 4; q++) acc[i][j][q] = 0.f;

    const uint32_t smbase = smem_u32(ksm);
    const int a_r = (lane & 7) + (lane >> 4) * 8;
    const int a_c = ((lane >> 3) & 1) * 8;
    const int b_r = (lane & 7) + ((lane >> 3) & 1) * 8;
    const int b_c = (lane >> 4) * 8;

    auto load_stage = [&](int stage, int n0) {
        uint32_t sb = smbase + stage * KKK_STAGE * 2;
        uint32_t sA1 = sb, sA2 = sb + KKK_A_TILE * 2;
#pragma unroll
        for (int l = 0; l < 4; l++) {       // 64 rows x 16 uint4 = 1024 slots
            int f = tid + l * 256;
            int r = f >> 4, c = (f & 15) * 8;
            cpa16(sA1 + (r * 136 + c) * 2, a1 + (size_t)(n0 + r) * RM + c);
            cpa16(sA2 + (r * 136 + c) * 2, a2 + (size_t)(n0 + r) * RM + c);
        }
    };

    load_stage(0, 0);
    CP_COMMIT();

    for (int chunk = 0; chunk < NCHUNK / KK_ROWS; chunk++) {
        if (chunk + 1 < NCHUNK / KK_ROWS) load_stage((chunk + 1) & 1, (chunk + 1) * KK_ROWS);
        CP_COMMIT();
        CP_WAIT1();
        __syncthreads();

        uint32_t sb = smbase + (chunk & 1) * KKK_STAGE * 2;
        uint32_t as1 = sb, as2 = sb + KKK_A_TILE * 2;
#pragma unroll
        for (int ks = 0; ks < 4; ks++) {
            uint32_t A1f[2][4], A2f[2][4], B1f[8][2];
#pragma unroll
            for (int mt = 0; mt < 2; mt++) {
                uint32_t off = ((ks * 16 + a_r) * 136 + wm * 32 + mt * 16 + a_c) * 2;
                ldmx4t(A1f[mt], as1 + off);
                ldmx4t(A2f[mt], as2 + off);
            }
#pragma unroll
            for (int nb = 0; nb < 4; nb++) {
                uint32_t off = ((ks * 16 + b_r) * 136
                                + wn * 64 + nb * 16 + b_c) * 2;
                uint32_t t1[4];
                ldmx4t(t1, as1 + off);
                B1f[nb * 2][0] = t1[0]; B1f[nb * 2][1] = t1[1];
                B1f[nb * 2 + 1][0] = t1[2]; B1f[nb * 2 + 1][1] = t1[3];
            }
#pragma unroll
            for (int mt = 0; mt < 2; mt++)
#pragma unroll
                for (int nt = 0; nt < 8; nt++) {
                    mma_f16(acc[mt][nt], A1f[mt], B1f[nt]);
                    mma_f16(acc[mt][nt], A2f[mt], B1f[nt]);
                }
        }
        __syncthreads();
    }

    float* dst = g_PART + ((size_t)split * BH + bh) * (RM * (RM + HD));
#pragma unroll
    for (int mt = 0; mt < 2; mt++)
#pragma unroll
        for (int nt = 0; nt < 8; nt++)
#pragma unroll
            for (int half = 0; half < 2; half++) {
                int m = wm * 32 + mt * 16 + (lane >> 2) + half * 8;
                int j = wn * 64 + nt * 8 + (lane & 3) * 2;
                *(float2*)&dst[m * (RM + HD) + j] =
                    make_float2(acc[mt][nt][half * 2], acc[mt][nt][half * 2 + 1]);
            }
}

// ---------------- kv via fp16 2-term HMMA (A=rf pair, B=v single) ----------------
#define KV_A_TILE (KK_ROWS*136)
#define KV_Y_TILE (KK_ROWS*72)
#define KV_STAGE (2*KV_A_TILE + KV_Y_TILE)
#define KV_SMEM (2*KV_STAGE*2)   // 88064 bytes

__global__ __launch_bounds__(256, 2)
void kv_hmma()
{
    extern __shared__ __half ksm[];
    const int tid = threadIdx.x, wid = tid >> 5, lane = tid & 31;
    const int bh = blockIdx.x, split = blockIdx.y;
    const int wm = wid >> 1, wn = wid & 1;

    size_t abase = ((size_t)bh * SEQ + (size_t)split * NCHUNK) * RM;
    const __half *a1 = g_RF1 + abase, *a2 = g_RF2 + abase;
    const __half *b1 = g_VB1 + ((size_t)bh * SEQ + (size_t)split * NCHUNK) * HD;

    float acc[2][4][4];
#pragma unroll
    for (int i = 0; i < 2; i++)
#pragma unroll
        for (int j = 0; j < 4; j++)
#pragma unroll
            for (int q = 0; q < 4; q++) acc[i][j][q] = 0.f;

    const uint32_t smbase = smem_u32(ksm);
    const int a_r = (lane & 7) + (lane >> 4) * 8;
    const int a_c = ((lane >> 3) & 1) * 8;
    const int b_r = (lane & 7) + ((lane >> 3) & 1) * 8;
    const int b_c = (lane >> 4) * 8;

    auto load_stage = [&](int stage, int n0) {
        uint32_t sb = smbase + stage * KV_STAGE * 2;
        uint32_t sA1 = sb, sA2 = sb + KV_A_TILE * 2;
        uint32_t sY1 = sb + 2 * KV_A_TILE * 2;
#pragma unroll
        for (int l = 0; l < 4; l++) {
            int f = tid + l * 256;
            int r = f >> 4, c = (f & 15) * 8;
            cpa16(sA1 + (r * 136 + c) * 2, a1 + (size_t)(n0 + r) * RM + c);
            cpa16(sA2 + (r * 136 + c) * 2, a2 + (size_t)(n0 + r) * RM + c);
        }
#pragma unroll
        for (int l = 0; l < 2; l++) {
            int f = tid + l * 256;
            int r = f >> 3, c = (f & 7) * 8;
            cpa16(sY1 + (r * 72 + c) * 2, b1 + (size_t)(n0 + r) * HD + c);
        }
    };

    load_stage(0, 0);
    CP_COMMIT();

    for (int chunk = 0; chunk < NCHUNK / KK_ROWS; chunk++) {
        if (chunk + 1 < NCHUNK / KK_ROWS) load_stage((chunk + 1) & 1, (chunk + 1) * KK_ROWS);
        CP_COMMIT();
        CP_WAIT1();
        __syncthreads();

        uint32_t sb = smbase + (chunk & 1) * KV_STAGE * 2;
        uint32_t as1 = sb, as2 = sb + KV_A_TILE * 2;
        uint32_t ys1 = sb + 2 * KV_A_TILE * 2;
#pragma unroll
        for (int ks = 0; ks < 4; ks++) {
            uint32_t A1f[2][4], A2f[2][4], B1f[4][2];
#pragma unroll
            for (int mt = 0; mt < 2; mt++) {
                uint32_t off = ((ks * 16 + a_r) * 136 + wm * 32 + mt * 16 + a_c) * 2;
                ldmx4t(A1f[mt], as1 + off);
                ldmx4t(A2f[mt], as2 + off);
            }
#pragma unroll
            for (int nb = 0; nb < 2; nb++) {
                uint32_t off = ((ks * 16 + b_r) * 72 + wn * 32 + nb * 16 + b_c) * 2;
                uint32_t t1[4];
                ldmx4t(t1, ys1 + off);
                B1f[nb * 2][0] = t1[0]; B1f[nb * 2][1] = t1[1];
                B1f[nb * 2 + 1][0] = t1[2]; B1f[nb * 2 + 1][1] = t1[3];
            }
#pragma unroll
            for (int mt = 0; mt < 2; mt++)
#pragma unroll
                for (int nt = 0; nt < 4; nt++) {
                    mma_f16(acc[mt][nt], A1f[mt], B1f[nt]);
                    mma_f16(acc[mt][nt], A2f[mt], B1f[nt]);
                }
        }
        __syncthreads();
    }

    float* dst = g_PART + ((size_t)split * BH + bh) * (RM * (RM + HD));
#pragma unroll
    for (int mt = 0; mt < 2; mt++)
#pragma unroll
        for (int nt = 0; nt < 4; nt++)
#pragma unroll
            for (int half = 0; half < 2; half++) {
                int m = wm * 32 + mt * 16 + (lane >> 2) + half * 8;
                int j = RM + wn * 32 + nt * 8 + (lane & 3) * 2;
                *(float2*)&dst[m * (RM + HD) + j] =
                    make_float2(acc[mt][nt][half * 2], acc[mt][nt][half * 2 + 1]);
            }
}

// ---------------- fused reduce + ISTA, split over d-halves -----------------------
__device__ __forceinline__ float softf(float z, float t)
{
    float a = fabsf(z) - t;
    return a > 0.f ? (z >= 0.f ? a : -a) : 0.f;
}

#define IST_SMEM ((RM*129 + RM*32 + RM*36) * 4)    // 100864 B

__global__ __launch_bounds__(256)
void ista_fused()
{
    extern __shared__ float sm[];
    float* kks = sm;
    float* kvs = sm + RM * 129;
    float* ss  = kvs + RM * 32;
    __shared__ float dsh[RM];
    __shared__ float rowsum[RM];
    __shared__ float Lsh;
    const int bh = blockIdx.x;
    const int dhalf = blockIdx.y;
    const float* part = g_PART;

    if (threadIdx.x < RM) {
        float s = 0.f;
#pragma unroll
        for (int sp = 0; sp < SPLITS; sp++)
            s += part[((size_t)sp * BH + bh) * (RM * (RM + HD))
                      + threadIdx.x * (RM + HD) + threadIdx.x];
        dsh[threadIdx.x] = 1.0f / fmaxf(sqrtf(s), 1e-12f);
    }
    __syncthreads();

    for (int idx = threadIdx.x; idx < RM * RM; idx += 256) {
        int m = idx >> 7, j = idx & 127;
        float s = 0.f;
#pragma unroll
        for (int sp = 0; sp < SPLITS; sp++)
            s += part[((size_t)sp * BH + bh) * (RM * (RM + HD)) + m * (RM + HD) + j];
        kks[m * 129 + j] = s * dsh[m] * dsh[j];
    }
    for (int idx = threadIdx.x; idx < RM * 32; idx += 256) {
        int m = idx >> 5, c = idx & 31;
        float s = 0.f;
#pragma unroll
        for (int sp = 0; sp < SPLITS; sp++)
            s += part[((size_t)sp * BH + bh) * (RM * (RM + HD))
                      + m * (RM + HD) + RM + dhalf * 32 + c];
        kvs[m * 32 + c] = s * dsh[m];
    }
    __syncthreads();

    if (threadIdx.x < RM) {
        float rs = 0.f;
        for (int j = 0; j < RM; j++) rs += fabsf(kks[threadIdx.x * 129 + j]);
        rowsum[threadIdx.x] = rs;
    }
    __syncthreads();
    if (threadIdx.x == 0) {
        float mx = 0.f;
        for (int i = 0; i < RM; i++) mx = fmaxf(mx, rowsum[i]);
        Lsh = mx + 1.0f;
    }
    __syncthreads();
    float invL = 1.0f / Lsh;
    float thr  = LAMBDA * invL;

    int m  = threadIdx.x >> 1;
    int cl = (threadIdx.x & 1) * 16;
#pragma unroll
    for (int i = 0; i < 16; i++)
        ss[m * 36 + cl + i] = softf(kvs[m * 32 + cl + i], LAMBDA);
    __syncthreads();

    for (int it = 0; it < NSTEP; it++) {
        float acc[16];
#pragma unroll
        for (int i = 0; i < 16; i++) acc[i] = 0.f;
        for (int p = 0; p < RM; p++) {
            float kv_ = kks[m * 129 + p];
            const float4* sp = (const float4*)&ss[p * 36 + cl];
#pragma unroll
            for (int q = 0; q < 4; q++) {
                float4 v = sp[q];
                acc[q * 4 + 0] += kv_ * v.x;
                acc[q * 4 + 1] += kv_ * v.y;
                acc[q * 4 + 2] += kv_ * v.z;
                acc[q * 4 + 3] += kv_ * v.w;
            }
        }
        float r[16];
#pragma unroll
        for (int i = 0; i < 16; i++) {
            float z = ss[m * 36 + cl + i] - (acc[i] - kvs[m * 32 + cl + i]) * invL;
            r[i] = softf(z, thr);
        }
        __syncthreads();
#pragma unroll
        for (int q = 0; q < 4; q++)
            *(float4*)&ss[m * 36 + cl + q * 4] =
                make_float4(r[q * 4], r[q * 4 + 1], r[q * 4 + 2], r[q * 4 + 3]);
        __syncthreads();
    }
    float dm = dsh[m];
#pragma unroll
    for (int q = 0; q < 4; q++) {
        float4 v = *(float4*)&ss[m * 36 + cl + q * 4];
        v.x *= dm; v.y *= dm; v.z *= dm; v.w *= dm;
        *(float4*)&ss[m * 36 + cl + q * 4] = v;
    }
    __syncthreads();
    int dl = threadIdx.x >> 3;
    int ms = (threadIdx.x & 7) * 16;
    size_t ob = ((size_t)bh * HD + dhalf * 32 + dl) * RM + ms;
#pragma unroll
    for (int i = 0; i < 16; i += 2) {
        float v0 = ss[(ms + i) * 36 + dl];
        float v1 = ss[(ms + i + 1) * 36 + dl];
        *(__half2*)&g_ST1[ob + i] =
            __halves2half2(__float2half(v0), __float2half(v1));
    }
}

// ---------------- out = rf(pair) @ sT(single) fp16 2-term, emits OC single --------
__global__ __launch_bounds__(256, 2)
void outgemm_hmma()
{
    __shared__ __half As1[128 * PITCH], As2[128 * PITCH];
    __shared__ __half Bs1[64 * PITCH];
    const int tid = threadIdx.x, wid = tid >> 5, lane = tid & 31;
    const int wm = wid & 3, wn = wid >> 2;
    const int bh = blockIdx.y, nblk = blockIdx.x;
    const int b = bh / NH, h = bh % NH;

    size_t rfbase = ((size_t)bh * SEQ + (size_t)nblk * 128) * RM;
    size_t stbase = (size_t)bh * HD * RM;

    float acc[2][4][4];
#pragma unroll
    for (int i = 0; i < 2; i++)
#pragma unroll
        for (int j = 0; j < 4; j++)
#pragma unroll
            for (int q = 0; q < 4; q++) acc[i][j][q] = 0.f;

    const uint32_t as1 = smem_u32(As1), as2 = smem_u32(As2);
    const uint32_t bs1 = smem_u32(Bs1);
    const int arow = wm * 32 + (lane & 15);
    const int acolL = (lane >> 4) * 8;
    const int bn   = wn * 32 + (lane & 7) + ((lane >> 4) & 1) * 8;
    const int bkL  = ((lane >> 3) & 1) * 8;

    for (int kc = 0; kc < 4; kc++) {
        const int k0 = kc * 32;
#pragma unroll
        for (int l = 0; l < 2; l++) {
            int f = tid + l * 256;
            int r = f >> 2, c = (f & 3) * 8;
            *(uint4*)(As1 + r * PITCH + c) =
                *(const uint4*)(g_RF1 + rfbase + (size_t)r * RM + k0 + c);
            *(uint4*)(As2 + r * PITCH + c) =
                *(const uint4*)(g_RF2 + rfbase + (size_t)r * RM + k0 + c);
        }
        {
            int r = tid >> 2, c = (tid & 3) * 8;
            if (r < 64)
                *(uint4*)(Bs1 + r * PITCH + c) =
                    *(const uint4*)(g_ST1 + stbase + (size_t)r * RM + k0 + c);
        }
        __syncthreads();
#pragma unroll
        for (int ks = 0; ks < 2; ks++) {
            const int acol = ks * 16 + acolL;
            const int bk   = ks * 16 + bkL;
            uint32_t a1[2][4], a2[2][4], b1[4][2];
#pragma unroll
            for (int mt = 0; mt < 2; mt++) {
                uint32_t off = ((arow + mt * 16) * PITCH + acol) * 2;
                ldmx4(a1[mt][0], a1[mt][1], a1[mt][2], a1[mt][3], as1 + off);
                ldmx4(a2[mt][0], a2[mt][1], a2[mt][2], a2[mt][3], as2 + off);
            }
#pragma unroll
            for (int nt2 = 0; nt2 < 2; nt2++) {
                uint32_t off = ((bn + nt2 * 16) * PITCH + bk) * 2;
                ldmx4(b1[nt2 * 2][0], b1[nt2 * 2][1],
                      b1[nt2 * 2 + 1][0], b1[nt2 * 2 + 1][1], bs1 + off);
            }
#pragma unroll
            for (int mt = 0; mt < 2; mt++)
#pragma unroll
                for (int nt = 0; nt < 4; nt++) {
                    mma_f16(acc[mt][nt], a1[mt], b1[nt]);
                    mma_f16(acc[mt][nt], a2[mt], b1[nt]);
                }
        }
        __syncthreads();
    }

    const int g  = lane >> 2;
    const int tg = lane & 3;
#pragma unroll
    for (int mt = 0; mt < 2; mt++)
#pragma unroll
        for (int nt = 0; nt < 4; nt++)
#pragma unroll
            for (int half = 0; half < 2; half++) {
                int nrow = nblk * 128 + wm * 32 + mt * 16 + g + half * 8;
                int d    = wn * 32 + nt * 8 + tg * 2;
                float2 v = make_float2(acc[mt][nt][half * 2],
                                       acc[mt][nt][half * 2 + 1]);
                size_t adr = ((size_t)b * SEQ + nrow) * CH + h * HD + d;
                *(__half2*)&g_OC1[adr] =
                    __halves2half2(__float2half(v.x), __float2half(v.y));
            }
}

// ---------------- launch -----------------------------------------------------------
extern "C" void kernel_launch(void* const* d_in, const int* in_sizes, int n_in,
                              void* d_out, int out_size)
{
    const float *x = nullptr, *wqkv = nullptr, *wproj = nullptr,
                *bias = nullptr, *rm = nullptr;
    for (int i = 0; i < n_in; i++) {
        const float* p = (const float*)d_in[i];
        switch (in_sizes[i]) {
            case BATCH * SEQ * CH: x = p; break;
            case CH * 2 * CH:      wqkv = p; break;
            case CH * CH:          wproj = p; break;
            case CH:               bias = p; break;
            case NH * HD * RM:     rm = p; break;
        }
    }
    float* out = (float*)d_out;
    (void)out_size;

    cudaFuncSetAttribute(hmma_gemm<0>, cudaFuncAttributeMaxDynamicSharedMemorySize, DG_SMEM);
    cudaFuncSetAttribute(hmma_gemm<1>, cudaFuncAttributeMaxDynamicSharedMemorySize, DG_SMEM);
    cudaFuncSetAttribute(rf_hmma, cudaFuncAttributeMaxDynamicSharedMemorySize, RF_SMEM);
    cudaFuncSetAttribute(kk_hmma, cudaFuncAttributeMaxDynamicSharedMemorySize, KKK_SMEM);
    cudaFuncSetAttribute(kv_hmma, cudaFuncAttributeMaxDynamicSharedMemorySize, KV_SMEM);
    cudaFuncSetAttribute(ista_fused, cudaFuncAttributeMaxDynamicSharedMemorySize, IST_SMEM);

    // conversions (all fp16)
    conv_x_kernel<<<BATCH * SEQ * CH / 1024, 256>>>(x);
    conv_small<<<(3 * CH * CH + NH * RM * HD) / 256, 256>>>(wqkv, wproj, rm);

    // 1. qkv = x @ Wqkv (q cols 2-term, v cols 1-term)
    hmma_gemm<0><<<dim3(12, 256), 256, DG_SMEM>>>(nullptr, nullptr, CH);
    // 2. rf (fp16 3-term, staged coalesced stores) -> rf fp16 pair
    rf_hmma<<<dim3(32, BH), 256, RF_SMEM>>>();
    // 3a. kk partials (full 128-j slab, B sliced from resident A tile)
    kk_hmma<<<dim3(BH, SPLITS), 256, KKK_SMEM>>>();
    // 3b. kv partials
    kv_hmma<<<dim3(BH, SPLITS), 256, KV_SMEM>>>();
    // 4. fused reduce + d + L + ISTA (split over d-halves) -> sT fp16 single
    ista_fused<<<dim3(BH, 2), 256, IST_SMEM>>>();
    // 5. out_head = rf @ s (fp16 2-term) -> OC fp16 single
    outgemm_hmma<<<dim3(32, BH), 256>>>();
    // 6. final projection + bias (fp16 1-term)
    hmma_gemm<1><<<dim3(6, 256), 256, DG_SMEM>>>(bias, out, CH);
}